// round 12
// baseline (speedup 1.0000x reference)
#include <cuda_runtime.h>
#include <cstdint>

#define T_LEN 8192
#define NLAG  64

// x buffer: 64 chunks of 128 values, stride 136 (pad 8) + 64-word zero chunk.
// stride 136 mod 32 = 8 -> fragment gathers hit all 32 banks (conflict-free).
#define XSTR   136
#define XWORDS (XSTR * 64 + 64)          // 8768 floats
#define BANDW  10240                     // 8 m-tiles x 16 rows x 80 cols fp32
#define DSMEM_BYTES (BANDW * 4)          // 40960 >= XWORDS*4 (35072)

__device__ __forceinline__ uint32_t tf32r(float x) {
    uint32_t r;
    asm("cvt.rna.tf32.f32 %0, %1;" : "=r"(r) : "f"(x));
    return r;
}
__device__ __forceinline__ void mma_tf32(float* c, const uint32_t* a,
                                         uint32_t b0, uint32_t b1) {
    asm volatile(
        "mma.sync.aligned.m16n8k8.row.col.f32.tf32.tf32.f32 "
        "{%0,%1,%2,%3}, {%4,%5,%6,%7}, {%8,%9}, {%0,%1,%2,%3};"
        : "+f"(c[0]), "+f"(c[1]), "+f"(c[2]), "+f"(c[3])
        : "r"(a[0]), "r"(a[1]), "r"(a[2]), "r"(a[3]), "r"(b0), "r"(b1));
}

__global__ __launch_bounds__(256, 2)
void autocorr_mma_kernel(const float* __restrict__ X, float* __restrict__ out)
{
    extern __shared__ __align__(16) float dsm[];
    float* xb   = dsm;                   // tf32-rounded centered row
    float* band = dsm;                   // aliased AFTER mainloop completes
    const uint32_t* xu = reinterpret_cast<const uint32_t*>(dsm);

    __shared__ float wsum[8], wsq[8];
    __shared__ float stats[2];           // [0]=mean, [1]=1/var0

    const int tid = threadIdx.x;
    const int wid = tid >> 5;
    const int lid = tid & 31;
    const int r4  = lid >> 2;            // fragment row index
    const int c4  = lid & 3;             // fragment k index
    const int b   = blockIdx.x;

    const float4* Xr = reinterpret_cast<const float4*>(X + (size_t)b * T_LEN);

    // ---------------- Phase 1: load row, mean & sumsq (exact fp32) ----------
    float4 xv[8];
    float s = 0.f, q = 0.f;
#pragma unroll
    for (int r = 0; r < 8; ++r) {
        xv[r] = Xr[tid + r * 256];
        s += xv[r].x + xv[r].y + xv[r].z + xv[r].w;
        q += xv[r].x * xv[r].x + xv[r].y * xv[r].y
           + xv[r].z * xv[r].z + xv[r].w * xv[r].w;
    }
#pragma unroll
    for (int o = 16; o > 0; o >>= 1) {
        s += __shfl_xor_sync(0xffffffffu, s, o);
        q += __shfl_xor_sync(0xffffffffu, q, o);
    }
    if (lid == 0) { wsum[wid] = s; wsq[wid] = q; }
    __syncthreads();
    if (tid == 0) {
        float S = 0.f, Q = 0.f;
#pragma unroll
        for (int i = 0; i < 8; ++i) { S += wsum[i]; Q += wsq[i]; }
        float mean = S * (1.f / (float)T_LEN);
        stats[0] = mean;
        stats[1] = 1.f / (Q - (float)T_LEN * mean * mean);  // 1/T cancels in ratio
    }
    __syncthreads();
    const float mean = stats[0];

    // ---------------- Phase 2: centered tf32 values -> padded xbuf ----------
#pragma unroll
    for (int r = 0; r < 8; ++r) {
        const int t0 = (tid + r * 256) * 4;
        const int ad = XSTR * (t0 >> 7) + (t0 & 127);   // 4 elems same chunk
        uint4 c;
        c.x = tf32r(xv[r].x - mean);
        c.y = tf32r(xv[r].y - mean);
        c.z = tf32r(xv[r].z - mean);
        c.w = tf32r(xv[r].w - mean);
        *reinterpret_cast<uint4*>(&xb[ad]) = c;
    }
    if (tid < NLAG) xb[XSTR * 64 + tid] = 0.f;          // zero chunk (t >= T)
    __syncthreads();

    // ---------------- Phase 3: band GEMM, k-split, 2 m-tiles/warp -----------
    // warp (g4, w4): ks in [4*g4, 4*g4+4), m-tiles {2*w4, 2*w4+1}.
    // B positions u0 = 32*w4 + 8j (j=0..11) serve both m-tiles; the A
    // fragments for both m-tiles ARE the j=0..3 B fragments (same matrix).
    const int g4 = wid >> 2;
    const int w4 = wid & 3;

    float C0[10][4], C1[10][4];
#pragma unroll
    for (int t = 0; t < 10; ++t)
#pragma unroll
        for (int j = 0; j < 4; ++j) { C0[t][j] = 0.f; C1[t][j] = 0.f; }

#pragma unroll
    for (int kk = 0; kk < 4; ++kk) {
        const int ks = 4 * g4 + kk;
        const int rowA = XSTR * (8 * ks + c4);
        const int rowB = rowA + XSTR * 4;

        uint32_t b0[12], b1[12];
#pragma unroll
        for (int j = 0; j < 12; ++j) {
            const int u0 = 32 * w4 + 8 * j;
            const int ub = u0 + ((u0 >= 128) ? 8 : 0) + r4;  // chunk-cross bump
            b0[j] = xu[rowA + ub];
            b1[j] = xu[rowB + ub];
        }
        // A fragments from the B pool (identical addresses)
        const uint32_t a0[4] = { b0[0], b0[1], b1[0], b1[1] };   // m-tile 2w4
        const uint32_t a1[4] = { b0[2], b0[3], b1[2], b1[3] };   // m-tile 2w4+1

#pragma unroll
        for (int j = 0; j < 12; ++j) {
            if (j < 10) mma_tf32(C0[j],     a0, b0[j], b1[j]);
            if (j >= 2) mma_tf32(C1[j - 2], a1, b0[j], b1[j]);
        }
    }
    __syncthreads();   // all warps done reading xbuf; band may now alias it

    // ---------------- Phase 4: C fragments -> band (group 0 write, 1 add) ---
    // m-tile mt band row layout: band[mt*1280 + row*80 + localcol]
    {
        float* bp0 = band + (2 * w4)     * 1280;
        float* bp1 = band + (2 * w4 + 1) * 1280;
        if (g4 == 0) {
#pragma unroll
            for (int t = 0; t < 10; ++t) {
                const int cb = 8 * t + 2 * c4;
                *reinterpret_cast<float2*>(&bp0[r4 * 80 + cb])       = make_float2(C0[t][0], C0[t][1]);
                *reinterpret_cast<float2*>(&bp0[(r4 + 8) * 80 + cb]) = make_float2(C0[t][2], C0[t][3]);
                *reinterpret_cast<float2*>(&bp1[r4 * 80 + cb])       = make_float2(C1[t][0], C1[t][1]);
                *reinterpret_cast<float2*>(&bp1[(r4 + 8) * 80 + cb]) = make_float2(C1[t][2], C1[t][3]);
            }
        }
        __syncthreads();
        if (g4 == 1) {
#pragma unroll
            for (int t = 0; t < 10; ++t) {
                const int cb = 8 * t + 2 * c4;
                float2* p;
                float2 v;
                p = reinterpret_cast<float2*>(&bp0[r4 * 80 + cb]);
                v = *p; v.x += C0[t][0]; v.y += C0[t][1]; *p = v;
                p = reinterpret_cast<float2*>(&bp0[(r4 + 8) * 80 + cb]);
                v = *p; v.x += C0[t][2]; v.y += C0[t][3]; *p = v;
                p = reinterpret_cast<float2*>(&bp1[r4 * 80 + cb]);
                v = *p; v.x += C1[t][0]; v.y += C1[t][1]; *p = v;
                p = reinterpret_cast<float2*>(&bp1[(r4 + 8) * 80 + cb]);
                v = *p; v.x += C1[t][2]; v.y += C1[t][3]; *p = v;
            }
        }
    }
    __syncthreads();

    // ---------------- Phase 5: diagonal reduce + normalize + store ----------
    if (tid < NLAG) {
        const int k = tid + 1;
        float acc = 0.f;
#pragma unroll
        for (int m = 0; m < 8; ++m) {
            const float* bp = band + m * 1280;
            float ps = 0.f;
#pragma unroll
            for (int r = 0; r < 16; ++r)
                ps += bp[r * 80 + r + k];   // local col - row = lag
            acc += ps;
        }
        out[(size_t)b * NLAG + tid] = acc * stats[1];
    }
}

extern "C" void kernel_launch(void* const* d_in, const int* in_sizes, int n_in,
                              void* d_out, int out_size)
{
    const float* X = (const float*)d_in[0];
    float* out = (float*)d_out;
    const int B = in_sizes[0] / T_LEN;   // 4096

    autocorr_mma_kernel<<<B, 256, DSMEM_BYTES>>>(X, out);
}

// round 13
// speedup vs baseline: 1.4402x; 1.4402x over previous
#include <cuda_runtime.h>
#include <cstdint>

#define T_LEN 8192
#define NLAG  64

// x buffer: 64 chunks of 128 values, stride 136 (pad 8) + 64-word zero chunk.
// stride 136 mod 32 = 8 -> fragment gathers (8*c4 + r4) hit all 32 banks.
#define XSTR   136
#define XWORDS (XSTR * 64 + 64)          // 8768 floats
#define BANDW  10240                     // 8 m-tiles x 16 rows x 80 cols fp32
#define DSMEM_BYTES (BANDW * 4)          // 40960 >= XWORDS*4 (35072)

__device__ __forceinline__ uint32_t tf32r(float x) {
    uint32_t r;
    asm("cvt.rna.tf32.f32 %0, %1;" : "=r"(r) : "f"(x));
    return r;
}
__device__ __forceinline__ void mma_tf32(float* c, const uint32_t* a,
                                         uint32_t b0, uint32_t b1) {
    asm volatile(
        "mma.sync.aligned.m16n8k8.row.col.f32.tf32.tf32.f32 "
        "{%0,%1,%2,%3}, {%4,%5,%6,%7}, {%8,%9}, {%0,%1,%2,%3};"
        : "+f"(c[0]), "+f"(c[1]), "+f"(c[2]), "+f"(c[3])
        : "r"(a[0]), "r"(a[1]), "r"(a[2]), "r"(a[3]), "r"(b0), "r"(b1));
}

__global__ __launch_bounds__(128, 4)
void autocorr_mma_kernel(const float* __restrict__ X, float* __restrict__ out)
{
    extern __shared__ __align__(16) float dsm[];
    float* xb   = dsm;                   // tf32-rounded centered row
    float* band = dsm;                   // aliased AFTER mainloop completes
    const uint32_t* xu = reinterpret_cast<const uint32_t*>(dsm);

    __shared__ float wsum[4], wsq[4];
    __shared__ float stats[2];           // [0]=mean, [1]=1/var0
    __shared__ float part[2][64];        // phase-5 partials

    const int tid = threadIdx.x;         // 0..127
    const int wid = tid >> 5;            // 0..3
    const int lid = tid & 31;
    const int r4  = lid >> 2;            // fragment row index
    const int c4  = lid & 3;             // fragment k index
    const int b   = blockIdx.x;

    const float4* Xr = reinterpret_cast<const float4*>(X + (size_t)b * T_LEN);

    // ---------------- Phase 1: load row, mean & sumsq (exact fp32) ----------
    float4 xv[16];
    float s = 0.f, q = 0.f;
#pragma unroll
    for (int r = 0; r < 16; ++r) {
        xv[r] = Xr[tid + r * 128];
        s += xv[r].x + xv[r].y + xv[r].z + xv[r].w;
        q += xv[r].x * xv[r].x + xv[r].y * xv[r].y
           + xv[r].z * xv[r].z + xv[r].w * xv[r].w;
    }
#pragma unroll
    for (int o = 16; o > 0; o >>= 1) {
        s += __shfl_xor_sync(0xffffffffu, s, o);
        q += __shfl_xor_sync(0xffffffffu, q, o);
    }
    if (lid == 0) { wsum[wid] = s; wsq[wid] = q; }
    __syncthreads();
    if (tid == 0) {
        float S = wsum[0] + wsum[1] + wsum[2] + wsum[3];
        float Q = wsq[0] + wsq[1] + wsq[2] + wsq[3];
        float mean = S * (1.f / (float)T_LEN);
        stats[0] = mean;
        stats[1] = 1.f / (Q - (float)T_LEN * mean * mean);  // 1/T cancels in ratio
    }
    __syncthreads();
    const float mean = stats[0];

    // ---------------- Phase 2: centered tf32 values -> padded xbuf ----------
#pragma unroll
    for (int r = 0; r < 16; ++r) {
        const int t0 = (tid + r * 128) * 4;
        const int ad = XSTR * (t0 >> 7) + (t0 & 127);   // 4 elems same chunk
        uint4 c;
        c.x = tf32r(xv[r].x - mean);
        c.y = tf32r(xv[r].y - mean);
        c.z = tf32r(xv[r].z - mean);
        c.w = tf32r(xv[r].w - mean);
        *reinterpret_cast<uint4*>(&xb[ad]) = c;
    }
    if (tid < NLAG) xb[XSTR * 64 + tid] = 0.f;          // zero chunk (t >= T)
    __syncthreads();

    // ---------------- Phase 3: band GEMM, 2 m-tiles per warp, full k --------
    // warp w: m-tiles {2w, 2w+1} (rows 32w..32w+31). B positions
    // u0 = 32w + 8j (j=0..11) serve both tiles; A-fragments for both tiles
    // ARE B pairs j=0..3 (u0 <= 32w+24 < 128, never bumped).
    float C0[10][4], C1[10][4];
#pragma unroll
    for (int t = 0; t < 10; ++t)
#pragma unroll
        for (int j = 0; j < 4; ++j) { C0[t][j] = 0.f; C1[t][j] = 0.f; }

#pragma unroll 1
    for (int ks = 0; ks < 8; ++ks) {
        const int rowA = XSTR * (8 * ks + c4);
        const int rowB = rowA + XSTR * 4;

        uint32_t b0[12], b1[12];
#pragma unroll
        for (int j = 0; j < 12; ++j) {
            const int u0 = 32 * wid + 8 * j;
            const int ub = u0 + ((u0 >= 128) ? 8 : 0) + r4;  // chunk-cross bump
            b0[j] = xu[rowA + ub];
            b1[j] = xu[rowB + ub];
        }
        const uint32_t a0[4] = { b0[0], b0[1], b1[0], b1[1] };   // m-tile 2w
        const uint32_t a1[4] = { b0[2], b0[3], b1[2], b1[3] };   // m-tile 2w+1

#pragma unroll
        for (int j = 0; j < 12; ++j) {
            if (j < 10) mma_tf32(C0[j],     a0, b0[j], b1[j]);
            if (j >= 2) mma_tf32(C1[j - 2], a1, b0[j], b1[j]);
        }
    }
    __syncthreads();   // all warps done reading xbuf; band may now alias it

    // ---------------- Phase 4: C fragments -> band (exclusive, no RMW) ------
    {
        float* bp0 = band + (2 * wid)     * 1280;
        float* bp1 = band + (2 * wid + 1) * 1280;
#pragma unroll
        for (int t = 0; t < 10; ++t) {
            const int cb = 8 * t + 2 * c4;
            *reinterpret_cast<float2*>(&bp0[r4 * 80 + cb])       = make_float2(C0[t][0], C0[t][1]);
            *reinterpret_cast<float2*>(&bp0[(r4 + 8) * 80 + cb]) = make_float2(C0[t][2], C0[t][3]);
            *reinterpret_cast<float2*>(&bp1[r4 * 80 + cb])       = make_float2(C1[t][0], C1[t][1]);
            *reinterpret_cast<float2*>(&bp1[(r4 + 8) * 80 + cb]) = make_float2(C1[t][2], C1[t][3]);
        }
    }
    __syncthreads();

    // ---------------- Phase 5: diagonal reduce + normalize + store ----------
    {
        const int h = tid >> 6;            // half: m-tiles 4h..4h+3
        const int k = (tid & 63) + 1;
        float acc = 0.f;
#pragma unroll
        for (int m = 0; m < 4; ++m) {
            const float* bp = band + (4 * h + m) * 1280;
            float ps = 0.f;
#pragma unroll
            for (int r = 0; r < 16; ++r)
                ps += bp[r * 80 + r + k];   // local col - row = lag
            acc += ps;
        }
        part[h][k - 1] = acc;
    }
    __syncthreads();
    if (tid < NLAG)
        out[(size_t)b * NLAG + tid] = (part[0][tid] + part[1][tid]) * stats[1];
}

extern "C" void kernel_launch(void* const* d_in, const int* in_sizes, int n_in,
                              void* d_out, int out_size)
{
    const float* X = (const float*)d_in[0];
    float* out = (float*)d_out;
    const int B = in_sizes[0] / T_LEN;   // 4096

    autocorr_mma_kernel<<<B, 128, DSMEM_BYTES>>>(X, out);
}